// round 15
// baseline (speedup 1.0000x reference)
#include <cuda_runtime.h>
#include <cuda_fp16.h>
#include <stdint.h>

// HSTU jagged causal attention — fp16 mma.sync m16n8k16, register-resident P,
// MMA2 k-split + end exchange (R12 core). K/V fp32->fp16 conversion is done
// CTA-LOCALLY: cp.async brings raw fp32 tiles into smem staging; each warp
// converts its rows into the swizzled fp16 operand buffers. No pre-pass
// kernel, no cross-CTA flags.
//   out[i] = sum_{j<=i} silu(q_i.k_j/sqrt(D))/max_seqlen * v_j  per (seq,head)
// H=8, D=DV=128, B=8, max_seqlen=1024.
//
// CTA: 64-row Q tile x (head,batch), 128 threads = 4 warps, warp (mh=w&1, nh=w>>1):
//  MMA1: m32 x n32 x k128 (A=Q ldsm, B=K ldsm)
//  P:    silu(C-frags) -> half2 pack (registers only; C-frag == A-frag layout)
//  MMA2: m32 x dv128 x k32 partial (A=P regs, B=V ldsm.trans); nh pairs swap
//        opposite dv-halves once at the end and sum.
// Smem 112KB: Q fp16 16K | Kh 16K | Vh 16K | Kstg fp32 32K | Vstg fp32 32K
// -> 2 CTAs/SM. fp16 buffers: 256B rows, 16B-chunk swizzle c^(r&7).

#define HD    1024
#define NTH   128
#define NTILES 16
#define ALPHA 0.08838834764831845f

#define SB_Q   0
#define SB_KH  16384
#define SB_VH  32768
#define SB_SK  49152
#define SB_SV  81920
#define SMEM_BYTES 114688      // 112 KB

__device__ __forceinline__ void mma_f16(float* c, const uint32_t* a,
                                        uint32_t b0, uint32_t b1) {
    asm volatile(
        "mma.sync.aligned.m16n8k16.row.col.f32.f16.f16.f32 "
        "{%0,%1,%2,%3}, {%4,%5,%6,%7}, {%8,%9}, {%0,%1,%2,%3};"
        : "+f"(c[0]), "+f"(c[1]), "+f"(c[2]), "+f"(c[3])
        : "r"(a[0]), "r"(a[1]), "r"(a[2]), "r"(a[3]), "r"(b0), "r"(b1));
}
__device__ __forceinline__ void ldsm4(uint32_t* d, uint32_t addr) {
    asm volatile("ldmatrix.sync.aligned.m8n8.x4.shared.b16 {%0,%1,%2,%3}, [%4];"
                 : "=r"(d[0]), "=r"(d[1]), "=r"(d[2]), "=r"(d[3]) : "r"(addr));
}
__device__ __forceinline__ void ldsm4t(uint32_t* d, uint32_t addr) {
    asm volatile("ldmatrix.sync.aligned.m8n8.x4.trans.shared.b16 {%0,%1,%2,%3}, [%4];"
                 : "=r"(d[0]), "=r"(d[1]), "=r"(d[2]), "=r"(d[3]) : "r"(addr));
}
__device__ __forceinline__ uint32_t smem_u32(const void* p) {
    uint32_t a;
    asm("{ .reg .u64 t; cvta.to.shared.u64 t, %1; cvt.u32.u64 %0, t; }"
        : "=r"(a) : "l"(p));
    return a;
}
__device__ __forceinline__ void cpa16(uint32_t dst, const float* src, int srcsz) {
    asm volatile("cp.async.cg.shared.global [%0], [%1], 16, %2;"
                 :: "r"(dst), "l"(src), "r"(srcsz) : "memory");
}
__device__ __forceinline__ uint32_t packh2(float lo, float hi) {
    __half2 h = __floats2half2_rn(lo, hi);
    return *(uint32_t*)&h;
}
#define CPA_COMMIT() asm volatile("cp.async.commit_group;" ::: "memory")
#define CPA_WAIT0()  asm volatile("cp.async.wait_group 0;" ::: "memory")

__global__ void __launch_bounds__(NTH, 2)
hstu_local_kernel(const float* __restrict__ tq, const float* __restrict__ tk,
                  const float* __restrict__ tv, const int* __restrict__ offsets,
                  const int* __restrict__ p_msl, const int* __restrict__ p_ssl,
                  float* __restrict__ out)
{
    extern __shared__ char smc[];
    const uint32_t smu = smem_u32(smc);

    const int b  = blockIdx.z;
    const int h  = blockIdx.y;
    const int it = (int)gridDim.x - 1 - (int)blockIdx.x;   // big tiles first

    const int off = offsets[b];
    const int len = offsets[b + 1] - off;
    const int i0  = it * 64;
    if (i0 >= len) return;

    const int msl = p_msl ? *p_msl : 1024;
    const int ssl = p_ssl ? *p_ssl : -1;
    const float rdenom = 1.0f / (float)((ssl > 0) ? ssl : msl);
    const float c_a = 0.5f * ALPHA;
    const float c_b = 0.5f * ALPHA * rdenom;

    const int tid  = threadIdx.x;
    const int w    = tid >> 5;
    const int lane = tid & 31;
    const int g    = lane >> 2;
    const int t4   = lane & 3;
    const int lq   = lane >> 3;
    const int lr   = lane & 7;
    const int mh   = w & 1;
    const int nh   = w >> 1;

    // ldmatrix lane bases (swizzle xor term = lr for every operand)
    const int ac  = lq >> 1;
    const int kc2 = lq & 1;
    const uint32_t qA0 = smu + SB_Q + (uint32_t)(mh * 32 + ((lq & 1) << 3) + lr) * 256;
    const uint32_t qA1 = qA0 + 16 * 256;
    const int krow     = nh * 32 + ((lq >> 1) << 3) + lr;
    const int vrow0    = ((lq & 1) << 3) + lr;
    const int vc       = lq >> 1;
    const uint32_t kB  = smu + SB_KH;
    const uint32_t vB  = smu + SB_VH;

    const float* kb = tk + (size_t)off * HD + h * 128;
    const float* vb = tv + (size_t)off * HD + h * 128;

    const int nj = it + 1;

    // ---- prologue: cp.async fp32 staging K0,V0; Q fp32->fp16 swizzled ----
    #pragma unroll
    for (int i2 = 0; i2 < 16; ++i2) {
        int idx = i2 * NTH + tid;  int r = idx >> 5;  int c = idx & 31;
        int ok = (r < len) ? 16 : 0;
        cpa16(smu + SB_SK + (uint32_t)(r * 512 + c * 16),
              kb + (size_t)(ok ? r : 0) * HD + c * 4, ok);
        cpa16(smu + SB_SV + (uint32_t)(r * 512 + c * 16),
              vb + (size_t)(ok ? r : 0) * HD + c * 4, ok);
    }
    CPA_COMMIT();
    {
        const float* qb = tq + (size_t)off * HD + h * 128;
        #pragma unroll
        for (int i2 = 0; i2 < 8; ++i2) {
            int idx = i2 * NTH + tid;  int r = idx >> 4;  int c = idx & 15;
            float4 v0 = make_float4(0.f, 0.f, 0.f, 0.f);
            float4 v1 = make_float4(0.f, 0.f, 0.f, 0.f);
            if (i0 + r < len) {
                const float* qr = qb + (size_t)(i0 + r) * HD + c * 8;
                v0 = *(const float4*)(qr);
                v1 = *(const float4*)(qr + 4);
            }
            uint4 t;
            t.x = packh2(v0.x, v0.y); t.y = packh2(v0.z, v0.w);
            t.z = packh2(v1.x, v1.y); t.w = packh2(v1.z, v1.w);
            *(uint4*)(smc + SB_Q + r * 256 + ((c ^ (r & 7)) << 4)) = t;
        }
    }

    float oacc[2][16][4];
    #pragma unroll
    for (int a = 0; a < 2; ++a)
        #pragma unroll
        for (int n = 0; n < 16; ++n)
            #pragma unroll
            for (int e = 0; e < 4; ++e) oacc[a][n][e] = 0.f;

    for (int jt = 0; jt < nj; ++jt) {
        const int j0 = jt * 64;

        CPA_WAIT0();              // fp32 staging[jt] landed
        __syncthreads();          // staging visible; fp16 bufs free (jt-1 read)

        // ---- convert staging -> swizzled fp16 Kh/Vh (warp w: rows 16w..) ----
        #pragma unroll
        for (int rr = 0; rr < 16; ++rr) {
            const int r = (w << 4) + rr;
            float4 fk = *(const float4*)(smc + SB_SK + r * 512 + lane * 16);
            float4 fv = *(const float4*)(smc + SB_SV + r * 512 + lane * 16);
            uint2 hk, hv;
            hk.x = packh2(fk.x, fk.y); hk.y = packh2(fk.z, fk.w);
            hv.x = packh2(fv.x, fv.y); hv.y = packh2(fv.z, fv.w);
            const uint32_t d = (uint32_t)((((lane >> 1) ^ (r & 7)) << 4) + (lane & 1) * 8);
            *(uint2*)(smc + SB_KH + r * 256 + d) = hk;
            *(uint2*)(smc + SB_VH + r * 256 + d) = hv;
        }
        __syncthreads();          // fp16 tiles visible; staging free

        // ---- MMA1: S[m32 x n32] = Q K^T, k=128 ----
        float sacc[2][4][4];
        #pragma unroll
        for (int a = 0; a < 2; ++a)
            #pragma unroll
            for (int n = 0; n < 4; ++n)
                #pragma unroll
                for (int e = 0; e < 4; ++e) sacc[a][n][e] = 0.f;

        #pragma unroll
        for (int ks = 0; ks < 8; ++ks) {
            const int kc = 2 * ks;
            uint32_t a0[4], a1[4], b0[4], b1[4];
            ldsm4(a0, qA0 + (uint32_t)(((kc + ac) ^ lr) << 4));
            ldsm4(a1, qA1 + (uint32_t)(((kc + ac) ^ lr) << 4));
            ldsm4(b0, kB + (uint32_t)(krow * 256        + (((kc + kc2) ^ lr) << 4)));
            ldsm4(b1, kB + (uint32_t)((krow + 16) * 256 + (((kc + kc2) ^ lr) << 4)));
            mma_f16(sacc[0][0], a0, b0[0], b0[1]);
            mma_f16(sacc[0][1], a0, b0[2], b0[3]);
            mma_f16(sacc[0][2], a0, b1[0], b1[1]);
            mma_f16(sacc[0][3], a0, b1[2], b1[3]);
            mma_f16(sacc[1][0], a1, b0[0], b0[1]);
            mma_f16(sacc[1][1], a1, b0[2], b0[3]);
            mma_f16(sacc[1][2], a1, b1[0], b1[1]);
            mma_f16(sacc[1][3], a1, b1[2], b1[3]);
        }

        // ---- prefetch fp32 staging[jt+1] (off the sync->MMA1 critical path) ----
        if (jt + 1 < nj) {
            const int j1 = j0 + 64;
            #pragma unroll
            for (int i2 = 0; i2 < 16; ++i2) {
                int idx = i2 * NTH + tid;  int r = idx >> 5;  int c = idx & 31;
                int gr = j1 + r;  int ok = (gr < len) ? 16 : 0;
                cpa16(smu + SB_SK + (uint32_t)(r * 512 + c * 16),
                      kb + (size_t)(ok ? gr : 0) * HD + c * 4, ok);
                cpa16(smu + SB_SV + (uint32_t)(r * 512 + c * 16),
                      vb + (size_t)(ok ? gr : 0) * HD + c * 4, ok);
            }
        }
        CPA_COMMIT();

        // ---- silu + (diag) mask -> P in registers (C-frag == A-frag) ----
        uint32_t pf[2][2][4];
        {
            const int diag = (jt == it);
            #pragma unroll
            for (int mf = 0; mf < 2; ++mf) {
                const int gi0 = i0 + mh * 32 + mf * 16 + g;
                #pragma unroll
                for (int nf = 0; nf < 4; ++nf) {
                    float p[4];
                    #pragma unroll
                    for (int e = 0; e < 4; ++e) {
                        float s = sacc[mf][nf][e];
                        float t;
                        asm("tanh.approx.f32 %0, %1;" : "=f"(t) : "f"(s * c_a));
                        float hx = s * c_b;
                        p[e] = fmaf(hx, t, hx);
                    }
                    if (diag) {
                        const int jc = j0 + nh * 32 + 8 * nf + 2 * t4;
                        p[0] = (gi0     >= jc)     ? p[0] : 0.f;
                        p[1] = (gi0     >= jc + 1) ? p[1] : 0.f;
                        p[2] = (gi0 + 8 >= jc)     ? p[2] : 0.f;
                        p[3] = (gi0 + 8 >= jc + 1) ? p[3] : 0.f;
                    }
                    pf[mf][nf >> 1][(nf & 1) * 2]     = packh2(p[0], p[1]);
                    pf[mf][nf >> 1][(nf & 1) * 2 + 1] = packh2(p[2], p[3]);
                }
            }
        }

        // ---- MMA2 partial: O[m32 x dv128] += P V over this warp's k=32 ----
        #pragma unroll
        for (int kg = 0; kg < 2; ++kg) {
            const uint32_t vba = vB + (uint32_t)(nh * 32 + 16 * kg + vrow0) * 256;
            #pragma unroll
            for (int q = 0; q < 8; ++q) {
                uint32_t bv[4];
                ldsm4t(bv, vba + (uint32_t)(((2 * q + vc) ^ lr) << 4));
                mma_f16(oacc[0][2 * q],     pf[0][kg], bv[0], bv[1]);
                mma_f16(oacc[0][2 * q + 1], pf[0][kg], bv[2], bv[3]);
                mma_f16(oacc[1][2 * q],     pf[1][kg], bv[0], bv[1]);
                mma_f16(oacc[1][2 * q + 1], pf[1][kg], bv[2], bv[3]);
            }
        }
    }

    // ---- epilogue: exchange opposite dv-halves between nh partners, sum ----
    __syncthreads();              // all fp16/staging reads done; reuse staging
    {
        char* wr = smc + SB_SK + w * 8192;
        const int base = (nh == 0) ? 8 : 0;   // send the half the partner owns
        #pragma unroll
        for (int mf = 0; mf < 2; ++mf)
            #pragma unroll
            for (int nf = 0; nf < 8; ++nf) {
                uint4 t;
                t.x = __float_as_uint(oacc[mf][base + nf][0]);
                t.y = __float_as_uint(oacc[mf][base + nf][1]);
                t.z = __float_as_uint(oacc[mf][base + nf][2]);
                t.w = __float_as_uint(oacc[mf][base + nf][3]);
                *(uint4*)(wr + (((mf * 8 + nf) * 32 + lane) << 4)) = t;
            }
    }
    __syncthreads();
    {
        const char* rd = smc + SB_SK + (w ^ 2) * 8192;
        const int keep = (nh == 0) ? 0 : 8;   // the half this warp finalizes
        #pragma unroll
        for (int mf = 0; mf < 2; ++mf) {
            const int r0 = i0 + mh * 32 + mf * 16 + g;
            const int r1 = r0 + 8;
            float* ob0 = out + (size_t)(off + r0) * HD + h * 128 + nh * 64 + 2 * t4;
            float* ob1 = out + (size_t)(off + r1) * HD + h * 128 + nh * 64 + 2 * t4;
            #pragma unroll
            for (int nf = 0; nf < 8; ++nf) {
                uint4 t = *(const uint4*)(rd + (((mf * 8 + nf) * 32 + lane) << 4));
                float f0 = oacc[mf][keep + nf][0] + __uint_as_float(t.x);
                float f1 = oacc[mf][keep + nf][1] + __uint_as_float(t.y);
                float f2 = oacc[mf][keep + nf][2] + __uint_as_float(t.z);
                float f3 = oacc[mf][keep + nf][3] + __uint_as_float(t.w);
                if (r0 < len) { float2 v; v.x = f0; v.y = f1; *(float2*)(ob0 + nf * 8) = v; }
                if (r1 < len) { float2 v; v.x = f2; v.y = f3; *(float2*)(ob1 + nf * 8) = v; }
            }
        }
    }
}

extern "C" void kernel_launch(void* const* d_in, const int* in_sizes, int n_in,
                              void* d_out, int out_size)
{
    const float* tq      = (const float*)d_in[0];
    const float* tk      = (const float*)d_in[1];
    const float* tv      = (const float*)d_in[2];
    const int*   offsets = (const int*)  d_in[3];
    const int*   p_msl   = (n_in > 4) ? (const int*)d_in[4] : nullptr;
    const int*   p_ssl   = (n_in > 5) ? (const int*)d_in[5] : nullptr;
    float*       out     = (float*)d_out;

    const int B = in_sizes[3] - 1;

    cudaFuncSetAttribute((const void*)hstu_local_kernel,
                         cudaFuncAttributeMaxDynamicSharedMemorySize, SMEM_BYTES);
    dim3 grid(NTILES, 8, B);
    hstu_local_kernel<<<grid, NTH, SMEM_BYTES>>>(tq, tk, tv, offsets,
                                                 p_msl, p_ssl, out);
}

// round 16
// speedup vs baseline: 1.1428x; 1.1428x over previous
#include <cuda_runtime.h>
#include <cuda_fp16.h>
#include <stdint.h>

// HSTU jagged causal attention — fp16 mma.sync m16n8k16, register-resident P
// (C-frag == A-frag), MMA2 k-split across warp pairs with one end exchange,
// cp.async double-buffered K/V, separate BW-bound fp32->fp16 cvt pre-kernel.
// R16: silu's tanh runs as tanh.approx.f16x2 (half the MUFU ops) on
// non-diagonal iterations; diagonal iteration keeps the exact fp32 path.
//   out[i] = sum_{j<=i} silu(q_i.k_j/sqrt(D))/max_seqlen * v_j  per (seq,head)
// H=8, D=DV=128, B=8, max_seqlen=1024.

#define HD    1024
#define NTH   128
#define NTILES 16
#define ALPHA 0.08838834764831845f

#define SB_Q  0
#define SB_K  16384
#define KSTG  16384
#define SB_V  49152
#define SMEM_BYTES 81920       // 80 KB -> 2 CTAs/SM

__device__ __align__(16) __half g_kh[(size_t)8192 * 1024];
__device__ __align__(16) __half g_vh[(size_t)8192 * 1024];

__global__ void __launch_bounds__(256)
cvt_kernel(const float* __restrict__ k, const float* __restrict__ v, int n4)
{
    int i = blockIdx.x * 256 + threadIdx.x;
    if (i >= n4) return;
    float4 a = ((const float4*)k)[i];
    float4 b = ((const float4*)v)[i];
    __half2 h0 = __floats2half2_rn(a.x, a.y);
    __half2 h1 = __floats2half2_rn(a.z, a.w);
    __half2 h2 = __floats2half2_rn(b.x, b.y);
    __half2 h3 = __floats2half2_rn(b.z, b.w);
    uint2 wk, wv;
    wk.x = *(uint32_t*)&h0;  wk.y = *(uint32_t*)&h1;
    wv.x = *(uint32_t*)&h2;  wv.y = *(uint32_t*)&h3;
    ((uint2*)g_kh)[i] = wk;
    ((uint2*)g_vh)[i] = wv;
}

__device__ __forceinline__ void mma_f16(float* c, const uint32_t* a,
                                        uint32_t b0, uint32_t b1) {
    asm volatile(
        "mma.sync.aligned.m16n8k16.row.col.f32.f16.f16.f32 "
        "{%0,%1,%2,%3}, {%4,%5,%6,%7}, {%8,%9}, {%0,%1,%2,%3};"
        : "+f"(c[0]), "+f"(c[1]), "+f"(c[2]), "+f"(c[3])
        : "r"(a[0]), "r"(a[1]), "r"(a[2]), "r"(a[3]), "r"(b0), "r"(b1));
}
__device__ __forceinline__ void ldsm4(uint32_t* d, uint32_t addr) {
    asm volatile("ldmatrix.sync.aligned.m8n8.x4.shared.b16 {%0,%1,%2,%3}, [%4];"
                 : "=r"(d[0]), "=r"(d[1]), "=r"(d[2]), "=r"(d[3]) : "r"(addr));
}
__device__ __forceinline__ void ldsm4t(uint32_t* d, uint32_t addr) {
    asm volatile("ldmatrix.sync.aligned.m8n8.x4.trans.shared.b16 {%0,%1,%2,%3}, [%4];"
                 : "=r"(d[0]), "=r"(d[1]), "=r"(d[2]), "=r"(d[3]) : "r"(addr));
}
__device__ __forceinline__ uint32_t smem_u32(const void* p) {
    uint32_t a;
    asm("{ .reg .u64 t; cvta.to.shared.u64 t, %1; cvt.u32.u64 %0, t; }"
        : "=r"(a) : "l"(p));
    return a;
}
__device__ __forceinline__ void cpa16(uint32_t dst, const __half* src, int srcsz) {
    asm volatile("cp.async.cg.shared.global [%0], [%1], 16, %2;"
                 :: "r"(dst), "l"(src), "r"(srcsz) : "memory");
}
__device__ __forceinline__ uint32_t packh2(float lo, float hi) {
    __half2 h = __floats2half2_rn(lo, hi);
    return *(uint32_t*)&h;
}
__device__ __forceinline__ uint32_t tanh_h2(uint32_t a) {
    uint32_t r;
    asm("tanh.approx.f16x2 %0, %1;" : "=r"(r) : "r"(a));
    return r;
}
#define CPA_COMMIT() asm volatile("cp.async.commit_group;" ::: "memory")
#define CPA_WAIT0()  asm volatile("cp.async.wait_group 0;" ::: "memory")

__global__ void __launch_bounds__(NTH, 2)
hstu_r16_kernel(const float* __restrict__ tq, const int* __restrict__ offsets,
                const int* __restrict__ p_msl, const int* __restrict__ p_ssl,
                float* __restrict__ out)
{
    extern __shared__ char smc[];
    const uint32_t smu = smem_u32(smc);

    const int b  = blockIdx.z;
    const int h  = blockIdx.y;
    const int it = (int)gridDim.x - 1 - (int)blockIdx.x;   // big tiles first

    const int off = offsets[b];
    const int len = offsets[b + 1] - off;
    const int i0  = it * 64;
    if (i0 >= len) return;

    const int msl = p_msl ? *p_msl : 1024;
    const int ssl = p_ssl ? *p_ssl : -1;
    const float rdenom = 1.0f / (float)((ssl > 0) ? ssl : msl);
    const float c_a = 0.5f * ALPHA;
    const float c_b = 0.5f * ALPHA * rdenom;

    const int tid  = threadIdx.x;
    const int w    = tid >> 5;
    const int lane = tid & 31;
    const int g    = lane >> 2;
    const int t4   = lane & 3;
    const int lq   = lane >> 3;
    const int lr   = lane & 7;
    const int mh   = w & 1;
    const int nh   = w >> 1;

    // ldmatrix lane bases (swizzle xor term = lr for every operand)
    const int ac  = lq >> 1;
    const int kc2 = lq & 1;
    const uint32_t qA0 = smu + SB_Q + (uint32_t)(mh * 32 + ((lq & 1) << 3) + lr) * 256;
    const uint32_t qA1 = qA0 + 16 * 256;
    const int krow     = nh * 32 + ((lq >> 1) << 3) + lr;
    const int vrow0    = ((lq & 1) << 3) + lr;
    const int vc       = lq >> 1;

    const __half* kb = g_kh + (size_t)off * HD + h * 128;
    const __half* vb = g_vh + (size_t)off * HD + h * 128;

    const int nj = it + 1;

    // ---- prologue: cp.async K0,V0 (stage 0); Q fp32->fp16 swizzled ----
    #pragma unroll
    for (int i2 = 0; i2 < 8; ++i2) {
        int idx = i2 * NTH + tid;  int r = idx >> 4;  int c = idx & 15;
        int ok = (r < len) ? 16 : 0;
        cpa16(smu + SB_K + (uint32_t)(r * 256 + ((c ^ (r & 7)) << 4)),
              kb + (size_t)(ok ? r : 0) * HD + c * 8, ok);
        cpa16(smu + SB_V + (uint32_t)(r * 256 + ((c ^ (r & 7)) << 4)),
              vb + (size_t)(ok ? r : 0) * HD + c * 8, ok);
    }
    CPA_COMMIT();
    {
        const float* qb = tq + (size_t)off * HD + h * 128;
        #pragma unroll
        for (int i2 = 0; i2 < 8; ++i2) {
            int idx = i2 * NTH + tid;  int r = idx >> 4;  int c = idx & 15;
            float4 v0 = make_float4(0.f, 0.f, 0.f, 0.f);
            float4 v1 = make_float4(0.f, 0.f, 0.f, 0.f);
            if (i0 + r < len) {
                const float* qr = qb + (size_t)(i0 + r) * HD + c * 8;
                v0 = *(const float4*)(qr);
                v1 = *(const float4*)(qr + 4);
            }
            uint4 t;
            t.x = packh2(v0.x, v0.y); t.y = packh2(v0.z, v0.w);
            t.z = packh2(v1.x, v1.y); t.w = packh2(v1.z, v1.w);
            *(uint4*)(smc + SB_Q + r * 256 + ((c ^ (r & 7)) << 4)) = t;
        }
    }

    float oacc[2][16][4];
    #pragma unroll
    for (int a = 0; a < 2; ++a)
        #pragma unroll
        for (int n = 0; n < 16; ++n)
            #pragma unroll
            for (int e = 0; e < 4; ++e) oacc[a][n][e] = 0.f;

    for (int jt = 0; jt < nj; ++jt) {
        const int j0 = jt * 64;
        const int st = jt & 1;
        const uint32_t kBs = smu + SB_K + (uint32_t)st * KSTG;
        const uint32_t vBs = smu + SB_V + (uint32_t)st * KSTG;

        CPA_WAIT0();
        __syncthreads();          // K/V[jt] visible; other stage free

        // prefetch {K,V}[jt+1]
        if (jt + 1 < nj) {
            const int j1 = j0 + 64;
            const uint32_t ko = SB_K + (uint32_t)(st ^ 1) * KSTG;
            const uint32_t vo = SB_V + (uint32_t)(st ^ 1) * KSTG;
            #pragma unroll
            for (int i2 = 0; i2 < 8; ++i2) {
                int idx = i2 * NTH + tid;  int r = idx >> 4;  int c = idx & 15;
                int gr = j1 + r;  int ok = (gr < len) ? 16 : 0;
                cpa16(smu + ko + (uint32_t)(r * 256 + ((c ^ (r & 7)) << 4)),
                      kb + (size_t)(ok ? gr : 0) * HD + c * 8, ok);
                cpa16(smu + vo + (uint32_t)(r * 256 + ((c ^ (r & 7)) << 4)),
                      vb + (size_t)(ok ? gr : 0) * HD + c * 8, ok);
            }
        }
        CPA_COMMIT();

        // ---- MMA1: S[m32 x n32] = Q K^T, k=128 ----
        float sacc[2][4][4];
        #pragma unroll
        for (int a = 0; a < 2; ++a)
            #pragma unroll
            for (int n = 0; n < 4; ++n)
                #pragma unroll
                for (int e = 0; e < 4; ++e) sacc[a][n][e] = 0.f;

        #pragma unroll
        for (int ks = 0; ks < 8; ++ks) {
            const int kc = 2 * ks;
            uint32_t a0[4], a1[4], b0[4], b1[4];
            ldsm4(a0, qA0 + (uint32_t)(((kc + ac) ^ lr) << 4));
            ldsm4(a1, qA1 + (uint32_t)(((kc + ac) ^ lr) << 4));
            ldsm4(b0, kBs + (uint32_t)(krow * 256        + (((kc + kc2) ^ lr) << 4)));
            ldsm4(b1, kBs + (uint32_t)((krow + 16) * 256 + (((kc + kc2) ^ lr) << 4)));
            mma_f16(sacc[0][0], a0, b0[0], b0[1]);
            mma_f16(sacc[0][1], a0, b0[2], b0[3]);
            mma_f16(sacc[0][2], a0, b1[0], b1[1]);
            mma_f16(sacc[0][3], a0, b1[2], b1[3]);
            mma_f16(sacc[1][0], a1, b0[0], b0[1]);
            mma_f16(sacc[1][1], a1, b0[2], b0[3]);
            mma_f16(sacc[1][2], a1, b1[0], b1[1]);
            mma_f16(sacc[1][3], a1, b1[2], b1[3]);
        }

        // ---- silu (+ diag mask) -> P in registers (C-frag == A-frag) ----
        uint32_t pf[2][2][4];
        if (jt != it) {
            // fast path: tanh.approx.f16x2 (2 elems per MUFU op); hx + final
            // fma stay fp32 so only the tanh itself is half precision.
            #pragma unroll
            for (int mf = 0; mf < 2; ++mf) {
                #pragma unroll
                for (int nf = 0; nf < 4; ++nf) {
                    float s0 = sacc[mf][nf][0], s1 = sacc[mf][nf][1];
                    float s2 = sacc[mf][nf][2], s3 = sacc[mf][nf][3];
                    uint32_t t01 = tanh_h2(packh2(s0 * c_a, s1 * c_a));
                    uint32_t t23 = tanh_h2(packh2(s2 * c_a, s3 * c_a));
                    float2 f01 = __half22float2(*(__half2*)&t01);
                    float2 f23 = __half22float2(*(__half2*)&t23);
                    float h0 = s0 * c_b, h1 = s1 * c_b;
                    float h2 = s2 * c_b, h3 = s3 * c_b;
                    float p0 = fmaf(h0, f01.x, h0);
                    float p1 = fmaf(h1, f01.y, h1);
                    float p2 = fmaf(h2, f23.x, h2);
                    float p3 = fmaf(h3, f23.y, h3);
                    pf[mf][nf >> 1][(nf & 1) * 2]     = packh2(p0, p1);
                    pf[mf][nf >> 1][(nf & 1) * 2 + 1] = packh2(p2, p3);
                }
            }
        } else {
            // diagonal tile: exact fp32 tanh + causal mask
            #pragma unroll
            for (int mf = 0; mf < 2; ++mf) {
                const int gi0 = i0 + mh * 32 + mf * 16 + g;
                #pragma unroll
                for (int nf = 0; nf < 4; ++nf) {
                    float p[4];
                    #pragma unroll
                    for (int e = 0; e < 4; ++e) {
                        float s = sacc[mf][nf][e];
                        float t;
                        asm("tanh.approx.f32 %0, %1;" : "=f"(t) : "f"(s * c_a));
                        float hx = s * c_b;
                        p[e] = fmaf(hx, t, hx);
                    }
                    const int jc = j0 + nh * 32 + 8 * nf + 2 * t4;
                    p[0] = (gi0     >= jc)     ? p[0] : 0.f;
                    p[1] = (gi0     >= jc + 1) ? p[1] : 0.f;
                    p[2] = (gi0 + 8 >= jc)     ? p[2] : 0.f;
                    p[3] = (gi0 + 8 >= jc + 1) ? p[3] : 0.f;
                    pf[mf][nf >> 1][(nf & 1) * 2]     = packh2(p[0], p[1]);
                    pf[mf][nf >> 1][(nf & 1) * 2 + 1] = packh2(p[2], p[3]);
                }
            }
        }

        // ---- MMA2 partial: O[m32 x dv128] += P V over this warp's k=32 ----
        #pragma unroll
        for (int kg = 0; kg < 2; ++kg) {
            const uint32_t vba = vBs + (uint32_t)(nh * 32 + 16 * kg + vrow0) * 256;
            #pragma unroll
            for (int q = 0; q < 8; ++q) {
                uint32_t bv[4];
                ldsm4t(bv, vba + (uint32_t)(((2 * q + vc) ^ lr) << 4));
                mma_f16(oacc[0][2 * q],     pf[0][kg], bv[0], bv[1]);
                mma_f16(oacc[0][2 * q + 1], pf[0][kg], bv[2], bv[3]);
                mma_f16(oacc[1][2 * q],     pf[1][kg], bv[0], bv[1]);
                mma_f16(oacc[1][2 * q + 1], pf[1][kg], bv[2], bv[3]);
            }
        }
    }

    // ---- epilogue: exchange opposite dv-halves between nh partners, sum ----
    __syncthreads();
    {
        char* wr = smc + SB_K + w * 8192;
        const int base = (nh == 0) ? 8 : 0;   // send the half the partner owns
        #pragma unroll
        for (int mf = 0; mf < 2; ++mf)
            #pragma unroll
            for (int nf = 0; nf < 8; ++nf) {
                uint4 t;
                t.x = __float_as_uint(oacc[mf][base + nf][0]);
                t.y = __float_as_uint(oacc[mf][base + nf][1]);
                t.z = __float_as_uint(oacc[mf][base + nf][2]);
                t.w = __float_as_uint(oacc[mf][base + nf][3]);
                *(uint4*)(wr + (((mf * 8 + nf) * 32 + lane) << 4)) = t;
            }
    }
    __syncthreads();
    {
        const char* rd = smc + SB_K + (w ^ 2) * 8192;
        const int keep = (nh == 0) ? 0 : 8;   // the half this warp finalizes
        #pragma unroll
        for (int mf = 0; mf < 2; ++mf) {
            const int r0 = i0 + mh * 32 + mf * 16 + g;
            const int r1 = r0 + 8;
            float* ob0 = out + (size_t)(off + r0) * HD + h * 128 + nh * 64 + 2 * t4;
            float* ob1 = out + (size_t)(off + r1) * HD + h * 128 + nh * 64 + 2 * t4;
            #pragma unroll
            for (int nf = 0; nf < 8; ++nf) {
                uint4 t = *(const uint4*)(rd + (((mf * 8 + nf) * 32 + lane) << 4));
                float f0 = oacc[mf][keep + nf][0] + __uint_as_float(t.x);
                float f1 = oacc[mf][keep + nf][1] + __uint_as_float(t.y);
                float f2 = oacc[mf][keep + nf][2] + __uint_as_float(t.z);
                float f3 = oacc[mf][keep + nf][3] + __uint_as_float(t.w);
                if (r0 < len) { float2 v; v.x = f0; v.y = f1; *(float2*)(ob0 + nf * 8) = v; }
                if (r1 < len) { float2 v; v.x = f2; v.y = f3; *(float2*)(ob1 + nf * 8) = v; }
            }
        }
    }
}

extern "C" void kernel_launch(void* const* d_in, const int* in_sizes, int n_in,
                              void* d_out, int out_size)
{
    const float* tq      = (const float*)d_in[0];
    const float* tk      = (const float*)d_in[1];
    const float* tv      = (const float*)d_in[2];
    const int*   offsets = (const int*)  d_in[3];
    const int*   p_msl   = (n_in > 4) ? (const int*)d_in[4] : nullptr;
    const int*   p_ssl   = (n_in > 5) ? (const int*)d_in[5] : nullptr;
    float*       out     = (float*)d_out;

    const int B  = in_sizes[3] - 1;
    const int n4 = in_sizes[1] / 4;

    cvt_kernel<<<(n4 + 255) / 256, 256>>>(tk, tv, n4);

    cudaFuncSetAttribute((const void*)hstu_r16_kernel,
                         cudaFuncAttributeMaxDynamicSharedMemorySize, SMEM_BYTES);
    dim3 grid(NTILES, 8, B);
    hstu_r16_kernel<<<grid, NTH, SMEM_BYTES>>>(tq, offsets, p_msl, p_ssl, out);
}

// round 17
// speedup vs baseline: 1.3777x; 1.2055x over previous
#include <cuda_runtime.h>
#include <cuda_fp16.h>
#include <stdint.h>

// HSTU jagged causal attention — fp16 mma.sync m16n8k16, register-resident P
// (C-frag == A-frag layout), MMA2 k-split across warp pairs with one
// end-of-kernel exchange, cp.async double-buffered K/V, BW-bound fp32->fp16
// cvt pre-kernel. R17 = R12 core (verbatim) + global LPT CTA ordering:
// 1-D grid, it = 15 - bid/64 -> all heaviest tiles scheduled first.
//   out[i] = sum_{j<=i} silu(q_i.k_j/sqrt(D))/max_seqlen * v_j  per (seq,head)
// H=8, D=DV=128, B=8, max_seqlen=1024.

#define HD    1024
#define NTH   128
#define NTILES 16
#define ALPHA 0.08838834764831845f

#define SB_Q  0
#define SB_K  16384
#define KSTG  16384
#define SB_V  49152
#define SMEM_BYTES 81920       // 80 KB -> 2 CTAs/SM

__device__ __align__(16) __half g_kh[(size_t)8192 * 1024];
__device__ __align__(16) __half g_vh[(size_t)8192 * 1024];

__global__ void __launch_bounds__(256)
cvt_kernel(const float* __restrict__ k, const float* __restrict__ v, int n4)
{
    int i = blockIdx.x * 256 + threadIdx.x;
    if (i >= n4) return;
    float4 a = ((const float4*)k)[i];
    float4 b = ((const float4*)v)[i];
    __half2 h0 = __floats2half2_rn(a.x, a.y);
    __half2 h1 = __floats2half2_rn(a.z, a.w);
    __half2 h2 = __floats2half2_rn(b.x, b.y);
    __half2 h3 = __floats2half2_rn(b.z, b.w);
    uint2 wk, wv;
    wk.x = *(uint32_t*)&h0;  wk.y = *(uint32_t*)&h1;
    wv.x = *(uint32_t*)&h2;  wv.y = *(uint32_t*)&h3;
    ((uint2*)g_kh)[i] = wk;
    ((uint2*)g_vh)[i] = wv;
}

__device__ __forceinline__ void mma_f16(float* c, const uint32_t* a,
                                        uint32_t b0, uint32_t b1) {
    asm volatile(
        "mma.sync.aligned.m16n8k16.row.col.f32.f16.f16.f32 "
        "{%0,%1,%2,%3}, {%4,%5,%6,%7}, {%8,%9}, {%0,%1,%2,%3};"
        : "+f"(c[0]), "+f"(c[1]), "+f"(c[2]), "+f"(c[3])
        : "r"(a[0]), "r"(a[1]), "r"(a[2]), "r"(a[3]), "r"(b0), "r"(b1));
}
__device__ __forceinline__ void ldsm4(uint32_t* d, uint32_t addr) {
    asm volatile("ldmatrix.sync.aligned.m8n8.x4.shared.b16 {%0,%1,%2,%3}, [%4];"
                 : "=r"(d[0]), "=r"(d[1]), "=r"(d[2]), "=r"(d[3]) : "r"(addr));
}
__device__ __forceinline__ void ldsm4t(uint32_t* d, uint32_t addr) {
    asm volatile("ldmatrix.sync.aligned.m8n8.x4.trans.shared.b16 {%0,%1,%2,%3}, [%4];"
                 : "=r"(d[0]), "=r"(d[1]), "=r"(d[2]), "=r"(d[3]) : "r"(addr));
}
__device__ __forceinline__ uint32_t smem_u32(const void* p) {
    uint32_t a;
    asm("{ .reg .u64 t; cvta.to.shared.u64 t, %1; cvt.u32.u64 %0, t; }"
        : "=r"(a) : "l"(p));
    return a;
}
__device__ __forceinline__ void cpa16(uint32_t dst, const __half* src, int srcsz) {
    asm volatile("cp.async.cg.shared.global [%0], [%1], 16, %2;"
                 :: "r"(dst), "l"(src), "r"(srcsz) : "memory");
}
__device__ __forceinline__ uint32_t packh2(float lo, float hi) {
    __half2 h = __floats2half2_rn(lo, hi);
    return *(uint32_t*)&h;
}
#define CPA_COMMIT() asm volatile("cp.async.commit_group;" ::: "memory")
#define CPA_WAIT0()  asm volatile("cp.async.wait_group 0;" ::: "memory")

__global__ void __launch_bounds__(NTH, 2)
hstu_lpt_kernel(const float* __restrict__ tq, const int* __restrict__ offsets,
                const int* __restrict__ p_msl, const int* __restrict__ p_ssl,
                float* __restrict__ out)
{
    extern __shared__ char smc[];
    const uint32_t smu = smem_u32(smc);

    // ---- global LPT ordering: heaviest row-tiles across ALL (b,h) first ----
    const int bid = (int)blockIdx.x;          // 0..1023
    const int it  = (NTILES - 1) - (bid >> 6);  // 15,15,...(x64),14,...,0
    const int bh  = bid & 63;
    const int b   = bh >> 3;
    const int h   = bh & 7;

    const int off = offsets[b];
    const int len = offsets[b + 1] - off;
    const int i0  = it * 64;
    if (i0 >= len) return;

    const int msl = p_msl ? *p_msl : 1024;
    const int ssl = p_ssl ? *p_ssl : -1;
    const float rdenom = 1.0f / (float)((ssl > 0) ? ssl : msl);
    const float c_a = 0.5f * ALPHA;
    const float c_b = 0.5f * ALPHA * rdenom;

    const int tid  = threadIdx.x;
    const int w    = tid >> 5;
    const int lane = tid & 31;
    const int g    = lane >> 2;
    const int t4   = lane & 3;
    const int lq   = lane >> 3;
    const int lr   = lane & 7;
    const int mh   = w & 1;
    const int nh   = w >> 1;

    // ldmatrix lane bases (swizzle xor term = lr for every operand)
    const int ac  = lq >> 1;
    const int kc2 = lq & 1;
    const uint32_t qA0 = smu + SB_Q + (uint32_t)(mh * 32 + ((lq & 1) << 3) + lr) * 256;
    const uint32_t qA1 = qA0 + 16 * 256;
    const int krow     = nh * 32 + ((lq >> 1) << 3) + lr;
    const int vrow0    = ((lq & 1) << 3) + lr;
    const int vc       = lq >> 1;

    const __half* kb = g_kh + (size_t)off * HD + h * 128;
    const __half* vb = g_vh + (size_t)off * HD + h * 128;

    const int nj = it + 1;

    // ---- prologue: cp.async K0,V0 (stage 0); Q fp32->fp16 swizzled ----
    #pragma unroll
    for (int i2 = 0; i2 < 8; ++i2) {
        int idx = i2 * NTH + tid;  int r = idx >> 4;  int c = idx & 15;
        int ok = (r < len) ? 16 : 0;
        cpa16(smu + SB_K + (uint32_t)(r * 256 + ((c ^ (r & 7)) << 4)),
              kb + (size_t)(ok ? r : 0) * HD + c * 8, ok);
        cpa16(smu + SB_V + (uint32_t)(r * 256 + ((c ^ (r & 7)) << 4)),
              vb + (size_t)(ok ? r : 0) * HD + c * 8, ok);
    }
    CPA_COMMIT();
    {
        const float* qb = tq + (size_t)off * HD + h * 128;
        #pragma unroll
        for (int i2 = 0; i2 < 8; ++i2) {
            int idx = i2 * NTH + tid;  int r = idx >> 4;  int c = idx & 15;
            float4 v0 = make_float4(0.f, 0.f, 0.f, 0.f);
            float4 v1 = make_float4(0.f, 0.f, 0.f, 0.f);
            if (i0 + r < len) {
                const float* qr = qb + (size_t)(i0 + r) * HD + c * 8;
                v0 = *(const float4*)(qr);
                v1 = *(const float4*)(qr + 4);
            }
            uint4 t;
            t.x = packh2(v0.x, v0.y); t.y = packh2(v0.z, v0.w);
            t.z = packh2(v1.x, v1.y); t.w = packh2(v1.z, v1.w);
            *(uint4*)(smc + SB_Q + r * 256 + ((c ^ (r & 7)) << 4)) = t;
        }
    }

    float oacc[2][16][4];
    #pragma unroll
    for (int a = 0; a < 2; ++a)
        #pragma unroll
        for (int n = 0; n < 16; ++n)
            #pragma unroll
            for (int e = 0; e < 4; ++e) oacc[a][n][e] = 0.f;

    for (int jt = 0; jt < nj; ++jt) {
        const int j0 = jt * 64;
        const int st = jt & 1;
        const uint32_t kBs = smu + SB_K + (uint32_t)st * KSTG;
        const uint32_t vBs = smu + SB_V + (uint32_t)st * KSTG;

        CPA_WAIT0();
        __syncthreads();          // K/V[jt] visible; other stage free

        // prefetch {K,V}[jt+1]
        if (jt + 1 < nj) {
            const int j1 = j0 + 64;
            const uint32_t ko = SB_K + (uint32_t)(st ^ 1) * KSTG;
            const uint32_t vo = SB_V + (uint32_t)(st ^ 1) * KSTG;
            #pragma unroll
            for (int i2 = 0; i2 < 8; ++i2) {
                int idx = i2 * NTH + tid;  int r = idx >> 4;  int c = idx & 15;
                int gr = j1 + r;  int ok = (gr < len) ? 16 : 0;
                cpa16(smu + ko + (uint32_t)(r * 256 + ((c ^ (r & 7)) << 4)),
                      kb + (size_t)(ok ? gr : 0) * HD + c * 8, ok);
                cpa16(smu + vo + (uint32_t)(r * 256 + ((c ^ (r & 7)) << 4)),
                      vb + (size_t)(ok ? gr : 0) * HD + c * 8, ok);
            }
        }
        CPA_COMMIT();

        // ---- MMA1: S[m32 x n32] = Q K^T, k=128 ----
        float sacc[2][4][4];
        #pragma unroll
        for (int a = 0; a < 2; ++a)
            #pragma unroll
            for (int n = 0; n < 4; ++n)
                #pragma unroll
                for (int e = 0; e < 4; ++e) sacc[a][n][e] = 0.f;

        #pragma unroll
        for (int ks = 0; ks < 8; ++ks) {
            const int kc = 2 * ks;
            uint32_t a0[4], a1[4], b0[4], b1[4];
            ldsm4(a0, qA0 + (uint32_t)(((kc + ac) ^ lr) << 4));
            ldsm4(a1, qA1 + (uint32_t)(((kc + ac) ^ lr) << 4));
            ldsm4(b0, kBs + (uint32_t)(krow * 256        + (((kc + kc2) ^ lr) << 4)));
            ldsm4(b1, kBs + (uint32_t)((krow + 16) * 256 + (((kc + kc2) ^ lr) << 4)));
            mma_f16(sacc[0][0], a0, b0[0], b0[1]);
            mma_f16(sacc[0][1], a0, b0[2], b0[3]);
            mma_f16(sacc[0][2], a0, b1[0], b1[1]);
            mma_f16(sacc[0][3], a0, b1[2], b1[3]);
            mma_f16(sacc[1][0], a1, b0[0], b0[1]);
            mma_f16(sacc[1][1], a1, b0[2], b0[3]);
            mma_f16(sacc[1][2], a1, b1[0], b1[1]);
            mma_f16(sacc[1][3], a1, b1[2], b1[3]);
        }

        // ---- silu + (diag) mask -> P in registers (C-frag == A-frag) ----
        uint32_t pf[2][2][4];
        {
            const int diag = (jt == it);
            #pragma unroll
            for (int mf = 0; mf < 2; ++mf) {
                const int gi0 = i0 + mh * 32 + mf * 16 + g;
                #pragma unroll
                for (int nf = 0; nf < 4; ++nf) {
                    float p[4];
                    #pragma unroll
                    for (int e = 0; e < 4; ++e) {
                        float s = sacc[mf][nf][e];
                        float t;
                        asm("tanh.approx.f32 %0, %1;" : "=f"(t) : "f"(s * c_a));
                        float hx = s * c_b;
                        p[e] = fmaf(hx, t, hx);
                    }
                    if (diag) {
                        const int jc = j0 + nh * 32 + 8 * nf + 2 * t4;
                        p[0] = (gi0     >= jc)     ? p[0] : 0.f;
                        p[1] = (gi0     >= jc + 1) ? p[1] : 0.f;
                        p[2] = (gi0 + 8 >= jc)     ? p[2] : 0.f;
                        p[3] = (gi0 + 8 >= jc + 1) ? p[3] : 0.f;
                    }
                    pf[mf][nf >> 1][(nf & 1) * 2]     = packh2(p[0], p[1]);
                    pf[mf][nf >> 1][(nf & 1) * 2 + 1] = packh2(p[2], p[3]);
                }
            }
        }

        // ---- MMA2 partial: O[m32 x dv128] += P V over this warp's k=32 ----
        #pragma unroll
        for (int kg = 0; kg < 2; ++kg) {
            const uint32_t vba = vBs + (uint32_t)(nh * 32 + 16 * kg + vrow0) * 256;
            #pragma unroll
            for (int q = 0; q < 8; ++q) {
                uint32_t bv[4];
                ldsm4t(bv, vba + (uint32_t)(((2 * q + vc) ^ lr) << 4));
                mma_f16(oacc[0][2 * q],     pf[0][kg], bv[0], bv[1]);
                mma_f16(oacc[0][2 * q + 1], pf[0][kg], bv[2], bv[3]);
                mma_f16(oacc[1][2 * q],     pf[1][kg], bv[0], bv[1]);
                mma_f16(oacc[1][2 * q + 1], pf[1][kg], bv[2], bv[3]);
            }
        }
    }

    // ---- epilogue: exchange opposite dv-halves between nh partners, sum ----
    __syncthreads();
    {
        char* wr = smc + SB_K + w * 8192;
        const int base = (nh == 0) ? 8 : 0;   // send the half the partner owns
        #pragma unroll
        for (int mf = 0; mf < 2; ++mf)
            #pragma unroll
            for (int nf = 0; nf < 8; ++nf) {
                uint4 t;
                t.x = __float_as_uint(oacc[mf][base + nf][0]);
                t.y = __float_as_uint(oacc[mf][base + nf][1]);
                t.z = __float_as_uint(oacc[mf][base + nf][2]);
                t.w = __float_as_uint(oacc[mf][base + nf][3]);
                *(uint4*)(wr + (((mf * 8 + nf) * 32 + lane) << 4)) = t;
            }
    }
    __syncthreads();
    {
        const char* rd = smc + SB_K + (w ^ 2) * 8192;
        const int keep = (nh == 0) ? 0 : 8;   // the half this warp finalizes
        #pragma unroll
        for (int mf = 0; mf < 2; ++mf) {
            const int r0 = i0 + mh * 32 + mf * 16 + g;
            const int r1 = r0 + 8;
            float* ob0 = out + (size_t)(off + r0) * HD + h * 128 + nh * 64 + 2 * t4;
            float* ob1 = out + (size_t)(off + r1) * HD + h * 128 + nh * 64 + 2 * t4;
            #pragma unroll
            for (int nf = 0; nf < 8; ++nf) {
                uint4 t = *(const uint4*)(rd + (((mf * 8 + nf) * 32 + lane) << 4));
                float f0 = oacc[mf][keep + nf][0] + __uint_as_float(t.x);
                float f1 = oacc[mf][keep + nf][1] + __uint_as_float(t.y);
                float f2 = oacc[mf][keep + nf][2] + __uint_as_float(t.z);
                float f3 = oacc[mf][keep + nf][3] + __uint_as_float(t.w);
                if (r0 < len) { float2 v; v.x = f0; v.y = f1; *(float2*)(ob0 + nf * 8) = v; }
                if (r1 < len) { float2 v; v.x = f2; v.y = f3; *(float2*)(ob1 + nf * 8) = v; }
            }
        }
    }
}

extern "C" void kernel_launch(void* const* d_in, const int* in_sizes, int n_in,
                              void* d_out, int out_size)
{
    const float* tq      = (const float*)d_in[0];
    const float* tk      = (const float*)d_in[1];
    const float* tv      = (const float*)d_in[2];
    const int*   offsets = (const int*)  d_in[3];
    const int*   p_msl   = (n_in > 4) ? (const int*)d_in[4] : nullptr;
    const int*   p_ssl   = (n_in > 5) ? (const int*)d_in[5] : nullptr;
    float*       out     = (float*)d_out;

    const int B  = in_sizes[3] - 1;
    const int n4 = in_sizes[1] / 4;

    cvt_kernel<<<(n4 + 255) / 256, 256>>>(tk, tv, n4);

    cudaFuncSetAttribute((const void*)hstu_lpt_kernel,
                         cudaFuncAttributeMaxDynamicSharedMemorySize, SMEM_BYTES);
    hstu_lpt_kernel<<<NTILES * 8 * B, NTH, SMEM_BYTES>>>(tq, offsets,
                                                         p_msl, p_ssl, out);
}